// round 12
// baseline (speedup 1.0000x reference)
#include <cuda_runtime.h>
#include <cuda_fp16.h>
#include <cstdint>
#include <math.h>

// Problem constants
#define NB   64     // batch
#define NT   256    // time
#define NK   5
#define NX   512
#define NH   512
#define NG   2048   // 4*H
#define NF   1024   // 2*X
#define BT   16384  // NB*NT

// fp16 GEMM tile config
#define BM   128
#define BN   128
#define BK   32
#define PITCH 40            // smem row pitch in halves (80B) -> ldmatrix conflict-free
#define NSTAGE 4

// scan config: 256 CTAs = 64 col-groups (8 cols) x 4 batch-groups (16 batches)
#define WPITCH 520

// ---------------- device scratch (static: no allocations allowed) ----------------
__device__ __half d_xa_h[(size_t)BT * NF];         // x_g_t, fp16
__device__ __half d_w_h[(size_t)NG * NF];          // W_ih fp16
__device__ __half d_whh_h[(size_t)NG * NH];        // W_hh fp16
__device__ __half d_hh_h[2][NB * NH];              // h ping-pong (fp16)
__device__ float d_pre[(size_t)NT * NB * NG];      // pre-gates, [t][b][g]
__device__ float d_houts[(size_t)NT * NB * NH];    // all h_t (fp32, for BN)
__device__ float d_scaleArr[NT];
__device__ float d_shiftArr[NT];
__device__ unsigned d_flag[256 * 32];              // per-CTA generation flags, 128B apart

// ---------------- mma / ldmatrix helpers ----------------
__device__ __forceinline__ uint32_t smem_u32(const void* p) {
    uint32_t a;
    asm("{ .reg .u64 t; cvta.to.shared.u64 t, %1; cvt.u32.u64 %0, t; }" : "=r"(a) : "l"(p));
    return a;
}
__device__ __forceinline__ void ldsm4(uint32_t* r, uint32_t addr) {
    asm volatile("ldmatrix.sync.aligned.m8n8.x4.shared.b16 {%0,%1,%2,%3}, [%4];"
                 : "=r"(r[0]), "=r"(r[1]), "=r"(r[2]), "=r"(r[3]) : "r"(addr));
}
__device__ __forceinline__ void mma16(float* c, const uint32_t* a, uint32_t b0, uint32_t b1) {
    asm volatile(
        "mma.sync.aligned.m16n8k16.row.col.f32.f16.f16.f32 "
        "{%0,%1,%2,%3}, {%4,%5,%6,%7}, {%8,%9}, {%0,%1,%2,%3};"
        : "+f"(c[0]), "+f"(c[1]), "+f"(c[2]), "+f"(c[3])
        : "r"(a[0]), "r"(a[1]), "r"(a[2]), "r"(a[3]), "r"(b0), "r"(b1));
}
__device__ __forceinline__ void cp16(uint32_t dst, const void* src) {
    asm volatile("cp.async.cg.shared.global [%0], [%1], 16;" :: "r"(dst), "l"(src) : "memory");
}
// fast gates: MUFU-based sigmoid/tanh (error ~1e-6, negligible vs 1.6e-4 budget)
__device__ __forceinline__ float sigmoid_f(float x) {
    return __fdividef(1.f, 1.f + __expf(-x));
}
__device__ __forceinline__ float tanh_f(float x) {
    return __fdividef(2.f, 1.f + __expf(-2.f * x)) - 1.f;
}

// ---------------- kernel 1: build x_g_t (fp16) ----------------
__global__ __launch_bounds__(256) void prep_kernel(const float* __restrict__ x) {
    int idx = blockIdx.x * blockDim.x + threadIdx.x;
    int f4 = idx & 255;
    int bt = idx >> 8;
    if (bt >= BT) return;
    int f = f4 * 4;
    const float* xb = x + (size_t)bt * (NK * NX);
    float4 v;
    if (f < NX) {
        v = *(const float4*)(xb + f);
    } else {
        int xr = f - NX;
        float4 a1 = *(const float4*)(xb + 1 * NX + xr);
        float4 a2 = *(const float4*)(xb + 2 * NX + xr);
        float4 a3 = *(const float4*)(xb + 3 * NX + xr);
        float4 a4 = *(const float4*)(xb + 4 * NX + xr);
        v.x = (a1.x + a2.x + a3.x + a4.x) * 0.25f;
        v.y = (a1.y + a2.y + a3.y + a4.y) * 0.25f;
        v.z = (a1.z + a2.z + a3.z + a4.z) * 0.25f;
        v.w = (a1.w + a2.w + a3.w + a4.w) * 0.25f;
    }
    __half2* ph = (__half2*)&d_xa_h[(size_t)bt * NF + f];
    ph[0] = __halves2half2(__float2half_rn(v.x), __float2half_rn(v.y));
    ph[1] = __halves2half2(__float2half_rn(v.z), __float2half_rn(v.w));
}

// ---------------- kernel 1b: convert W_ih to fp16 ----------------
__global__ __launch_bounds__(256) void wconv_kernel(const float* __restrict__ Wih) {
    int idx = (blockIdx.x * 256 + threadIdx.x) * 4;
    float4 v = *(const float4*)(Wih + idx);
    __half2* ph = (__half2*)&d_w_h[idx];
    ph[0] = __halves2half2(__float2half_rn(v.x), __float2half_rn(v.y));
    ph[1] = __halves2half2(__float2half_rn(v.z), __float2half_rn(v.w));
}

// ---------------- kernel 1c: convert W_hh to fp16 ----------------
__global__ __launch_bounds__(256) void whhconv_kernel(const float* __restrict__ Whh) {
    int idx = (blockIdx.x * 256 + threadIdx.x) * 4;   // over NG*NH
    float4 v = *(const float4*)(Whh + idx);
    __half2* ph = (__half2*)&d_whh_h[idx];
    ph[0] = __halves2half2(__float2half_rn(v.x), __float2half_rn(v.y));
    ph[1] = __halves2half2(__float2half_rn(v.z), __float2half_rn(v.w));
}

// ---------------- kernel 2: fp16 tensor-core GEMM (unchanged from R10) ----------------
__global__ __launch_bounds__(256, 2) void gemm16_kernel(const float* __restrict__ bih,
                                                        const float* __restrict__ bhh) {
    extern __shared__ __half hsm[];
    const uint32_t sbase = smem_u32(hsm);
    const int MAT   = BM * PITCH;    // 5120 halves per matrix
    const int STG_H = 2 * MAT;       // halves per stage (A, B)

    const int tid = threadIdx.x;
    const int wid = tid >> 5;
    const int lid = tid & 31;
    const int g   = lid >> 2;
    const int tig = lid & 3;
    const int warpM = wid >> 1;
    const int warpN = wid & 1;
    const int ntile = blockIdx.x;
    const int mtile = blockIdx.y;

    float accH[2][8][4];
#pragma unroll
    for (int i = 0; i < 2; i++)
#pragma unroll
        for (int j = 0; j < 8; j++)
#pragma unroll
            for (int q = 0; q < 4; q++) accH[i][j][q] = 0.f;

    auto prefetch = [&](int i) {
        const int k0 = i * BK;
        const uint32_t sb = sbase + (uint32_t)((i & (NSTAGE - 1)) * STG_H) * 2;
#pragma unroll
        for (int j = 0; j < 4; j++) {
            int c = tid + j * 256;
            int mat = c >> 9, rem = c & 511;
            int row = rem >> 2, part = rem & 3;
            const __half* src = (mat == 0) ? d_xa_h + (size_t)(mtile * BM + row) * NF
                                           : d_w_h + (size_t)(ntile * BN + row) * NF;
            cp16(sb + (uint32_t)(mat * MAT + row * PITCH + part * 8) * 2, src + k0 + part * 8);
        }
        asm volatile("cp.async.commit_group;" ::: "memory");
    };

    prefetch(0); prefetch(1); prefetch(2);
    for (int i = 0; i < NF / BK; i++) {
        if (i <= 29)      asm volatile("cp.async.wait_group 2;" ::: "memory");
        else if (i == 30) asm volatile("cp.async.wait_group 1;" ::: "memory");
        else              asm volatile("cp.async.wait_group 0;" ::: "memory");
        __syncthreads();
        if (i < 29) prefetch(i + 3);

        const uint32_t boff = sbase + (uint32_t)((i & (NSTAGE - 1)) * STG_H) * 2;
#pragma unroll
        for (int ks = 0; ks < 2; ks++) {
            uint32_t ah[2][4];
            {
                int arow = (lid & 7) + ((lid >> 3) & 1) * 8;
                int akc = ks * 16 + (lid >> 4) * 8;
#pragma unroll
                for (int mf = 0; mf < 2; mf++) {
                    int row = warpM * 32 + mf * 16 + arow;
                    ldsm4(ah[mf], boff + (uint32_t)(row * PITCH + akc) * 2);
                }
            }
            int brow0 = (lid & 7) + ((lid >> 4) & 1) * 8;
            int bkc = ks * 16 + ((lid >> 3) & 1) * 8;
            uint32_t bh[2][4];
            {
                int row = warpN * 64 + brow0;
                ldsm4(bh[0], boff + (uint32_t)(MAT + row * PITCH + bkc) * 2);
            }
#pragma unroll
            for (int p = 0; p < 4; p++) {
                int cur = p & 1, nxt = cur ^ 1;
                if (p < 3) {
                    int row = warpN * 64 + (p + 1) * 16 + brow0;
                    ldsm4(bh[nxt], boff + (uint32_t)(MAT + row * PITCH + bkc) * 2);
                }
#pragma unroll
                for (int mf = 0; mf < 2; mf++) {
                    mma16(accH[mf][2 * p],     ah[mf], bh[cur][0], bh[cur][1]);
                    mma16(accH[mf][2 * p + 1], ah[mf], bh[cur][2], bh[cur][3]);
                }
            }
        }
    }

#pragma unroll
    for (int nf = 0; nf < 8; nf++) {
        int n = ntile * BN + warpN * 64 + nf * 8 + tig * 2;
        float bias0 = bih[n] + bhh[n];
        float bias1 = bih[n + 1] + bhh[n + 1];
#pragma unroll
        for (int mf = 0; mf < 2; mf++) {
            int m0 = mtile * BM + warpM * 32 + mf * 16 + g;
            int m1 = m0 + 8;
            {
                int b = m0 >> 8, t = m0 & 255;
                float2 v = make_float2(accH[mf][nf][0] + bias0, accH[mf][nf][1] + bias1);
                *(float2*)&d_pre[((size_t)t * NB + b) * NG + n] = v;
            }
            {
                int b = m1 >> 8, t = m1 & 255;
                float2 v = make_float2(accH[mf][nf][2] + bias0, accH[mf][nf][3] + bias1);
                *(float2*)&d_pre[((size_t)t * NB + b) * NG + n] = v;
            }
        }
    }
}

// ---------------- kernel 3: tensor-core persistent scan, 256 CTAs x 256 threads ----------------
// cid = bg*64 + hg.  hg 0..63 -> 8 h-columns; bg 0..3 -> 16 batches.  2 CTAs/SM.
//   threads 0-127 (cells):    pv prefetch, matvec, gates, h store, release
//   threads 128-255 (stagers): per-thread flag wait + h staging, matvec
__global__ __launch_bounds__(256) void scan_kernel() {
    extern __shared__ char smraw[];
    __half* WsH = (__half*)smraw;                 // 32 x 520
    __half* HsH = WsH + 32 * WPITCH;              // 16 x 520
    float*  zb  = (float*)(HsH + 16 * WPITCH);    // 2 x 32 x 17
    unsigned* sbase_p = (unsigned*)(zb + 2 * 32 * 17);

    const int tid = threadIdx.x;
    const int cid = blockIdx.x;
    const int hg = cid & 63;
    const int bg = cid >> 6;

    if (tid == 0) {
        unsigned b;
        asm volatile("ld.acquire.gpu.global.u32 %0, [%1];" : "=r"(b) : "l"(&d_flag[cid * 32]) : "memory");
        *sbase_p = b;
    }

    // load W_hh slice: 32 rows (r = q*8+cs -> G = q*512 + hg*8 + cs) x 512
    for (int i = tid; i < 2048; i += 256) {
        int r = i >> 6, k8 = (i & 63) * 8;
        int G = (r >> 3) * NH + hg * 8 + (r & 7);
        *(uint4*)&WsH[r * WPITCH + k8] = *(const uint4*)&d_whh_h[(size_t)G * NH + k8];
    }
    // zero h staging (h_{-1} = 0): 16*520 halves = 1040 uint4
    for (int i = tid; i < 1040; i += 256) {
        ((uint4*)HsH)[i] = make_uint4(0u, 0u, 0u, 0u);
    }
    __syncthreads();
    const unsigned base = *sbase_p;

    // matvec warp mapping: 8 warps = 2(kh) x 2(m) x 2(n)
    const int lid = tid & 31;
    const int wid = tid >> 5;
    const int kh = wid >> 2;
    const int mq = wid & 1;
    const int nq = (wid >> 1) & 1;
    const uint32_t sb32 = smem_u32(smraw);
    const int arow = mq * 16 + (lid & 7) + ((lid >> 3) & 1) * 8;
    const uint32_t a_base = sb32 + (uint32_t)(arow * WPITCH + kh * 256 + (lid >> 4) * 8) * 2;
    const int brow = nq * 8 + (lid & 7);
    const uint32_t b_base = sb32 + (uint32_t)(32 * WPITCH) * 2
                          + (uint32_t)(brow * WPITCH + kh * 256 + ((lid >> 3) & 3) * 8) * 2;

    // cell mapping (tid < 128)
    const int colsub = tid & 7;
    const int bsub = (tid >> 3) & 15;
    const int col = hg * 8 + colsub;
    const int bb = bg * 16 + bsub;
    float c = 0.f;

    // stager mapping (tid >= 128): one col-chunk (8 cols) x 8 batch rows, ONE flag
    const int tp = tid & 127;
    const int cc = tp >> 1;                 // producer col-group 0..63
    const int rg = (tp & 1) * 8;            // batch rows rg..rg+8
    const unsigned* myflag = &d_flag[(bg * 64 + cc) * 32];

    for (int t = 0; t < NT; t++) {
        float pv0 = 0.f, pv1 = 0.f, pv2 = 0.f, pv3 = 0.f;
        if (tid < 128) {
            const float* pr = d_pre + ((size_t)t * NB + bb) * NG + col;
            pv0 = pr[0]; pv1 = pr[512]; pv2 = pr[1024]; pv3 = pr[1536];
        } else if (t > 0) {
            unsigned target = base + (unsigned)t;
            unsigned v;
            do {
                asm volatile("ld.acquire.gpu.global.u32 %0, [%1];" : "=r"(v) : "l"(myflag) : "memory");
            } while ((int)(v - target) < 0);
            const __half* srcH = d_hh_h[(t + 1) & 1];
#pragma unroll
            for (int j = 0; j < 8; j++) {
                int r = rg + j;
                *(uint4*)&HsH[r * WPITCH + cc * 8] = *(const uint4*)&srcH[(bg * 16 + r) * NH + cc * 8];
            }
        }
        __syncthreads();   // staged h visible to all matvec warps

        // matvec: 16 k-steps per warp; B ldsm4 spans 2 k-steps
        float aH[4] = {0, 0, 0, 0};
        uint32_t aaddr = a_base, baddr = b_base;
#pragma unroll
        for (int kk2 = 0; kk2 < 8; kk2++) {
            uint32_t a0[4], a1[4], bh[4];
            ldsm4(a0, aaddr);
            ldsm4(a1, aaddr + 32);
            ldsm4(bh, baddr);
            mma16(aH, a0, bh[0], bh[1]);
            mma16(aH, a1, bh[2], bh[3]);
            aaddr += 64; baddr += 64;
        }
        {
            float* z = zb + kh * (32 * 17);
            int zr = mq * 16 + (lid >> 2);
            int zc = nq * 8 + (lid & 3) * 2;
            z[zr * 17 + zc]           = aH[0];
            z[zr * 17 + zc + 1]       = aH[1];
            z[(zr + 8) * 17 + zc]     = aH[2];
            z[(zr + 8) * 17 + zc + 1] = aH[3];
        }
        __syncthreads();   // zb visible to cells

        if (tid < 128) {
            float zi = zb[(0 * 8 + colsub) * 17 + bsub] + zb[32 * 17 + (0 * 8 + colsub) * 17 + bsub] + pv0;
            float zf = zb[(1 * 8 + colsub) * 17 + bsub] + zb[32 * 17 + (1 * 8 + colsub) * 17 + bsub] + pv1;
            float zg = zb[(2 * 8 + colsub) * 17 + bsub] + zb[32 * 17 + (2 * 8 + colsub) * 17 + bsub] + pv2;
            float zo = zb[(3 * 8 + colsub) * 17 + bsub] + zb[32 * 17 + (3 * 8 + colsub) * 17 + bsub] + pv3;
            float ig = sigmoid_f(zi);
            float fg = sigmoid_f(zf);
            float gg = tanh_f(zg);
            float og = sigmoid_f(zo);
            c = fg * c + ig * gg;
            float hv = og * tanh_f(c);
            d_hh_h[t & 1][bb * NH + col] = __float2half_rn(hv);
            asm volatile("bar.sync 1, 128;" ::: "memory");   // cells only
            if (tid == 0) {
                asm volatile("st.release.gpu.global.u32 [%0], %1;"
                             :: "l"(&d_flag[cid * 32]), "r"(base + (unsigned)t + 1u) : "memory");
            }
            d_houts[(size_t)t * (NB * NH) + bb * NH + col] = hv;
        }
        // stagers proceed straight to next step's flag wait (overlaps cells' gate phase)
    }
}

// ---------------- kernel 4: per-t BN stats -> scale/shift ----------------
__global__ __launch_bounds__(256) void stats_kernel(const float* __restrict__ gamma,
                                                    const float* __restrict__ beta) {
    int t = blockIdx.x;
    const float4* p = (const float4*)(d_houts + (size_t)t * (NB * NH));
    float s = 0.f, ss = 0.f;
    for (int i = threadIdx.x; i < (NB * NH) / 4; i += 256) {
        float4 v = p[i];
        s  += v.x + v.y + v.z + v.w;
        ss += v.x * v.x + v.y * v.y + v.z * v.z + v.w * v.w;
    }
#pragma unroll
    for (int o = 16; o > 0; o >>= 1) {
        s  += __shfl_down_sync(0xffffffffu, s, o);
        ss += __shfl_down_sync(0xffffffffu, ss, o);
    }
    __shared__ float rs[8], rss[8];
    int w = threadIdx.x >> 5;
    if ((threadIdx.x & 31) == 0) { rs[w] = s; rss[w] = ss; }
    __syncthreads();
    if (threadIdx.x == 0) {
        float S = 0.f, SS = 0.f;
#pragma unroll
        for (int i = 0; i < 8; i++) { S += rs[i]; SS += rss[i]; }
        float mean = S * (1.f / (NB * NH));
        float var = SS * (1.f / (NB * NH)) - mean * mean;
        float sc = gamma[t] * rsqrtf(var + 1e-5f);
        d_scaleArr[t] = sc;
        d_shiftArr[t] = beta[t] - mean * sc;
    }
}

// ---------------- kernel 5: elu(BN(h)) mean over t -> out[b][h] ----------------
__global__ __launch_bounds__(256) void final_kernel(float* __restrict__ out) {
    int idx = blockIdx.x * 256 + threadIdx.x;
    float acc = 0.f;
#pragma unroll 4
    for (int t = 0; t < NT; t++) {
        float v = d_houts[(size_t)t * (NB * NH) + idx];
        float u = v * d_scaleArr[t] + d_shiftArr[t];
        acc += (u > 0.f) ? u : expm1f(u);
    }
    out[idx] = acc * (1.f / NT);
}

// ---------------- launch ----------------
extern "C" void kernel_launch(void* const* d_in, const int* in_sizes, int n_in,
                              void* d_out, int out_size) {
    const float* x     = (const float*)d_in[0];
    const float* Wih   = (const float*)d_in[1];
    const float* Whh   = (const float*)d_in[2];
    const float* bih   = (const float*)d_in[3];
    const float* bhh   = (const float*)d_in[4];
    const float* gamma = (const float*)d_in[5];
    const float* beta  = (const float*)d_in[6];
    float* out = (float*)d_out;

    prep_kernel<<<BT, 256>>>(x);
    wconv_kernel<<<(NG * NF / 4) / 256, 256>>>(Wih);
    whhconv_kernel<<<(NG * NH / 4) / 256, 256>>>(Whh);

    int gsmem = NSTAGE * 2 * BM * PITCH * 2;   // 81,920 B -> 2 CTAs/SM
    cudaFuncSetAttribute(gemm16_kernel, cudaFuncAttributeMaxDynamicSharedMemorySize, gsmem);
    dim3 ggrid(NG / BN, BT / BM);              // (16, 128)
    gemm16_kernel<<<ggrid, 256, gsmem>>>(bih, bhh);

    int ssmem = (32 * WPITCH + 16 * WPITCH) * 2 + 2 * 32 * 17 * 4 + 16;   // 54,288 B -> 2 CTAs/SM
    cudaFuncSetAttribute(scan_kernel, cudaFuncAttributeMaxDynamicSharedMemorySize, ssmem);
    scan_kernel<<<256, 256, ssmem>>>();

    stats_kernel<<<NT, 256>>>(gamma, beta);
    final_kernel<<<(NB * NH) / 256, 256>>>(out);
}